// round 4
// baseline (speedup 1.0000x reference)
#include <cuda_runtime.h>
#include <cuda_fp16.h>
#include <cstdint>
#include <math.h>

#define BB 4
#define SS 2048
#define DD 1024
#define HH 1024
#define SCALEF 0.125f
#define MR (BB * SS)          // 8192

// ---------------- scratch (allocation-free rule) ----------------
__device__ __half s_Qh[MR * DD], s_Ql[MR * DD];
__device__ __half s_Kh[MR * DD], s_Kl[MR * DD];
__device__ __half s_Vh[MR * DD], s_Vl[MR * DD];
__device__ __half s_Wqh[HH * DD], s_Wql[HH * DD];
__device__ __half s_Wkh[HH * DD], s_Wkl[HH * DD];
__device__ __half s_Wvh[HH * DD], s_Wvl[HH * DD];
__device__ __half s_Woh[DD * HH], s_Wol[DD * HH];
__device__ __half g_qh[MR * HH], g_ql[MR * HH];
__device__ __half g_kh[MR * HH], g_kl[MR * HH];
__device__ __half g_vh[MR * HH], g_vl[MR * HH];   // natural [b][s][h]
__device__ float  g_sc[BB * SS * SS];
__device__ __half g_wh[BB * SS * SS], g_wl[BB * SS * SS];
__device__ __half g_ch[MR * HH], g_cl[MR * HH];
__device__ float  g_pm[BB * 8 * SS], g_ps[BB * 8 * SS];
__device__ float  g_cm[BB * SS], g_ci[BB * SS];

// ---------------- helpers ----------------
__device__ __forceinline__ uint32_t smem_u32(const void* p) {
    uint32_t a;
    asm("{ .reg .u64 t; cvta.to.shared.u64 t, %1; cvt.u32.u64 %0, t; }" : "=r"(a) : "l"(p));
    return a;
}
#define LDSM4(r, a) \
    asm volatile("ldmatrix.sync.aligned.m8n8.x4.shared.b16 {%0,%1,%2,%3}, [%4];" \
        : "=r"((r)[0]), "=r"((r)[1]), "=r"((r)[2]), "=r"((r)[3]) : "r"(a))
#define LDSM4T(r, a) \
    asm volatile("ldmatrix.sync.aligned.m8n8.x4.trans.shared.b16 {%0,%1,%2,%3}, [%4];" \
        : "=r"((r)[0]), "=r"((r)[1]), "=r"((r)[2]), "=r"((r)[3]) : "r"(a))
#define CP16(d, s) asm volatile("cp.async.cg.shared.global [%0], [%1], 16;" :: "r"(d), "l"(s))
#define CPCOMMIT() asm volatile("cp.async.commit_group;" ::: "memory")
#define CPWAIT1()  asm volatile("cp.async.wait_group 1;" ::: "memory")

__device__ __forceinline__ void mma16816(float* c, const uint32_t* a, const uint32_t* b) {
    asm volatile("mma.sync.aligned.m16n8k16.row.col.f32.f16.f16.f32 "
        "{%0,%1,%2,%3}, {%4,%5,%6,%7}, {%8,%9}, {%0,%1,%2,%3};"
        : "+f"(c[0]), "+f"(c[1]), "+f"(c[2]), "+f"(c[3])
        : "r"(a[0]), "r"(a[1]), "r"(a[2]), "r"(a[3]), "r"(b[0]), "r"(b[1]));
}

__device__ __forceinline__ void wr_split(__half* H, __half* L, long idx, float v0, float v1) {
    __half2 h = __floats2half2_rn(v0, v1);
    __half2 l = __floats2half2_rn(v0 - __low2float(h), v1 - __high2float(h));
    *reinterpret_cast<__half2*>(H + idx) = h;
    *reinterpret_cast<__half2*>(L + idx) = l;
}

// ---------------- fp32 -> hi/lo fp16 split ----------------
__global__ __launch_bounds__(256) void split_f32(const float4* __restrict__ x,
                                                 __half2* __restrict__ hi,
                                                 __half2* __restrict__ lo, int n4)
{
    int i = blockIdx.x * 256 + threadIdx.x;
    if (i >= n4) return;
    float4 v = x[i];
    __half2 h0 = __floats2half2_rn(v.x, v.y);
    __half2 h1 = __floats2half2_rn(v.z, v.w);
    __half2 l0 = __floats2half2_rn(v.x - __low2float(h0), v.y - __high2float(h0));
    __half2 l1 = __floats2half2_rn(v.z - __low2float(h1), v.w - __high2float(h1));
    hi[2 * i] = h0; hi[2 * i + 1] = h1;
    lo[2 * i] = l0; lo[2 * i + 1] = l1;
}

// ---------------- NT GEMM: C = alpha*A*B^T (+bias), A[M,K] B[N,K] split fp16 ----------------
// tile 128x128x32, 8 warps (2m x 4n), 3-stage cp.async pipeline.
#define NT_AL 10240
#define NT_BH 20480
#define NT_BL 30720
#define NT_STG 40960
#define NT_SMEM (3 * NT_STG)

__global__ __launch_bounds__(256, 1) void gemm_nt(
    const __half* __restrict__ Ah, const __half* __restrict__ Al,
    const __half* __restrict__ Bh, const __half* __restrict__ Bl,
    const float* __restrict__ bias, float* __restrict__ Cf,
    __half* __restrict__ Ch, __half* __restrict__ Cl,
    int M, int N, int K, long sA, long sB, long sC, float alpha)
{
    extern __shared__ char smem[];
    const uint32_t sb = smem_u32(smem);
    const int tid = threadIdx.x;
    const int lane = tid & 31;
    const int wid = tid >> 5;
    const int wm = wid & 1, wn = wid >> 1;

    Ah += (long)blockIdx.z * sA;  Al += (long)blockIdx.z * sA;
    Bh += (long)blockIdx.z * sB;  Bl += (long)blockIdx.z * sB;
    const int rowBase = blockIdx.y * 128;
    const int colBase = blockIdx.x * 128;
    const __half* Aph = Ah + (long)rowBase * K;
    const __half* Apl = Al + (long)rowBase * K;
    const __half* Bph = Bh + (long)colBase * K;
    const __half* Bpl = Bl + (long)colBase * K;

    const int nch = K >> 5;

    // issue one stage of cp.async (4 operand tiles, 2 granules/thread each)
    auto issue = [&](int st, int k0) {
        const uint32_t sm = sb + st * NT_STG;
#pragma unroll
        for (int h = 0; h < 2; h++) {
            int idx = tid + (h << 8);
            int row = idx >> 2;
            int ch8 = (idx & 3) << 3;               // half offset within 32-col row
            uint32_t so = sm + row * 80 + ch8 * 2;
            long go = (long)row * K + k0 + ch8;
            CP16(so,          (const char*)(Aph + go));
            CP16(so + NT_AL,  (const char*)(Apl + go));
            CP16(so + NT_BH,  (const char*)(Bph + go));
            CP16(so + NT_BL,  (const char*)(Bpl + go));
        }
    };

    issue(0, 0);  CPCOMMIT();
    issue(1, 32); CPCOMMIT();

    float acc[4][4][4] = {};

    for (int c = 0; c < nch; c++) {
        CPWAIT1();
        __syncthreads();
        if (c + 2 < nch) issue((c + 2) % 3, (c + 2) << 5);
        CPCOMMIT();

        const uint32_t base = sb + (c % 3) * NT_STG;
#pragma unroll
        for (int ks = 0; ks < 2; ks++) {
            uint32_t ah[4][4], al[4][4], bh[2][4], bl[2][4];
            const int kcA = ks * 16 + ((lane >> 4) << 3);
            const int mr = wm * 64 + (lane & 15);
#pragma unroll
            for (int mt = 0; mt < 4; mt++) {
                uint32_t ad = base + (mr + mt * 16) * 80 + kcA * 2;
                LDSM4(ah[mt], ad);
                LDSM4(al[mt], ad + NT_AL);
            }
            const int nr = wn * 32 + (lane & 7) + ((lane >> 4) << 3);
            const int kcB = ks * 16 + (((lane >> 3) & 1) << 3);
#pragma unroll
            for (int np = 0; np < 2; np++) {
                uint32_t bd = base + NT_BH + (nr + np * 16) * 80 + kcB * 2;
                LDSM4(bh[np], bd);
                LDSM4(bl[np], bd + (NT_BL - NT_BH));
            }
#pragma unroll
            for (int mt = 0; mt < 4; mt++)
#pragma unroll
                for (int nt = 0; nt < 4; nt++) {
                    const uint32_t* fh = &bh[nt >> 1][(nt & 1) * 2];
                    const uint32_t* fl = &bl[nt >> 1][(nt & 1) * 2];
                    mma16816(acc[mt][nt], ah[mt], fh);
                    mma16816(acc[mt][nt], ah[mt], fl);
                    mma16816(acc[mt][nt], al[mt], fh);
                }
        }
    }

    // epilogue
    float* Cfz = Cf ? Cf + (long)blockIdx.z * sC : nullptr;
    __half* Chz = Ch ? Ch + (long)blockIdx.z * sC : nullptr;
    __half* Clz = Cl ? Cl + (long)blockIdx.z * sC : nullptr;
#pragma unroll
    for (int mt = 0; mt < 4; mt++) {
        const int r0 = rowBase + wm * 64 + mt * 16 + (lane >> 2);
#pragma unroll
        for (int nt = 0; nt < 4; nt++) {
            const int c0 = colBase + wn * 32 + nt * 8 + (lane & 3) * 2;
            float v0 = acc[mt][nt][0] * alpha, v1 = acc[mt][nt][1] * alpha;
            float v2 = acc[mt][nt][2] * alpha, v3 = acc[mt][nt][3] * alpha;
            if (bias) {
                float b0 = __ldg(bias + c0), b1 = __ldg(bias + c0 + 1);
                v0 += b0; v1 += b1; v2 += b0; v3 += b1;
            }
            if (Cfz) {
                *reinterpret_cast<float2*>(Cfz + (long)r0 * N + c0)       = make_float2(v0, v1);
                *reinterpret_cast<float2*>(Cfz + (long)(r0 + 8) * N + c0) = make_float2(v2, v3);
            } else {
                wr_split(Chz, Clz, (long)r0 * N + c0, v0, v1);
                wr_split(Chz, Clz, (long)(r0 + 8) * N + c0, v2, v3);
            }
        }
    }
}

// ---------------- NN GEMM: C = A*B (+split out), A[M,K] split, B[K,N] split ----------------
// B staged [32 k-rows][128 n-cols], 272B row stride; ldmatrix.trans for B frags.
#define NN_AL 10240
#define NN_BH 20480
#define NN_BL 29184
#define NN_STG 37888
#define NN_SMEM (3 * NN_STG)

__global__ __launch_bounds__(256, 1) void gemm_nn(
    const __half* __restrict__ Ah, const __half* __restrict__ Al,
    const __half* __restrict__ Bh, const __half* __restrict__ Bl,
    __half* __restrict__ Ch, __half* __restrict__ Cl,
    int M, int N, int K, long sA, long sB, long sC)
{
    extern __shared__ char smem[];
    const uint32_t sb = smem_u32(smem);
    const int tid = threadIdx.x;
    const int lane = tid & 31;
    const int wid = tid >> 5;
    const int wm = wid & 1, wn = wid >> 1;

    Ah += (long)blockIdx.z * sA;  Al += (long)blockIdx.z * sA;
    Bh += (long)blockIdx.z * sB;  Bl += (long)blockIdx.z * sB;
    const int rowBase = blockIdx.y * 128;
    const int colBase = blockIdx.x * 128;
    const __half* Aph = Ah + (long)rowBase * K;
    const __half* Apl = Al + (long)rowBase * K;
    const __half* Bph = Bh + colBase;
    const __half* Bpl = Bl + colBase;

    const int nch = K >> 5;

    auto issue = [&](int st, int k0) {
        const uint32_t sm = sb + st * NN_STG;
#pragma unroll
        for (int h = 0; h < 2; h++) {
            int idx = tid + (h << 8);
            // A tile: [128 rows m][32 cols k], 80B rows
            int ra = idx >> 2;
            int ca8 = (idx & 3) << 3;
            uint32_t soa = sm + ra * 80 + ca8 * 2;
            long goa = (long)ra * K + k0 + ca8;
            CP16(soa,         (const char*)(Aph + goa));
            CP16(soa + NN_AL, (const char*)(Apl + goa));
            // B tile: [32 rows k][128 cols n], 272B rows
            int rb = idx >> 4;
            int cb8 = (idx & 15) << 3;
            uint32_t sob = sm + NN_BH + rb * 272 + cb8 * 2;
            long gob = (long)(k0 + rb) * N + cb8;
            CP16(sob,                     (const char*)(Bph + gob));
            CP16(sob + (NN_BL - NN_BH),   (const char*)(Bpl + gob));
        }
    };

    issue(0, 0);  CPCOMMIT();
    issue(1, 32); CPCOMMIT();

    float acc[4][4][4] = {};

    for (int c = 0; c < nch; c++) {
        CPWAIT1();
        __syncthreads();
        if (c + 2 < nch) issue((c + 2) % 3, (c + 2) << 5);
        CPCOMMIT();

        const uint32_t base = sb + (c % 3) * NN_STG;
#pragma unroll
        for (int ks = 0; ks < 2; ks++) {
            uint32_t ah[4][4], al[4][4], bh[2][4], bl[2][4];
            const int kcA = ks * 16 + ((lane >> 4) << 3);
            const int mr = wm * 64 + (lane & 15);
#pragma unroll
            for (int mt = 0; mt < 4; mt++) {
                uint32_t ad = base + (mr + mt * 16) * 80 + kcA * 2;
                LDSM4(ah[mt], ad);
                LDSM4(al[mt], ad + NN_AL);
            }
            // trans B: lanes 0-15 -> k rows (ks*16 + lane&15) at n0; lanes 16-31 same k at n0+8
            const int klB = ks * 16 + (lane & 15);
#pragma unroll
            for (int np = 0; np < 2; np++) {
                const int nlB = wn * 32 + np * 16 + ((lane >> 4) << 3);
                uint32_t bd = base + NN_BH + klB * 272 + nlB * 2;
                LDSM4T(bh[np], bd);
                LDSM4T(bl[np], bd + (NN_BL - NN_BH));
            }
#pragma unroll
            for (int mt = 0; mt < 4; mt++)
#pragma unroll
                for (int nt = 0; nt < 4; nt++) {
                    const uint32_t* fh = &bh[nt >> 1][(nt & 1) * 2];
                    const uint32_t* fl = &bl[nt >> 1][(nt & 1) * 2];
                    mma16816(acc[mt][nt], ah[mt], fh);
                    mma16816(acc[mt][nt], ah[mt], fl);
                    mma16816(acc[mt][nt], al[mt], fh);
                }
        }
    }

    __half* Chz = Ch + (long)blockIdx.z * sC;
    __half* Clz = Cl + (long)blockIdx.z * sC;
#pragma unroll
    for (int mt = 0; mt < 4; mt++) {
        const int r0 = rowBase + wm * 64 + mt * 16 + (lane >> 2);
#pragma unroll
        for (int nt = 0; nt < 4; nt++) {
            const int c0 = colBase + wn * 32 + nt * 8 + (lane & 3) * 2;
            wr_split(Chz, Clz, (long)r0 * N + c0, acc[mt][nt][0], acc[mt][nt][1]);
            wr_split(Chz, Clz, (long)(r0 + 8) * N + c0, acc[mt][nt][2], acc[mt][nt][3]);
        }
    }
}

// ---------------- split softmax over QUERY axis ----------------
__global__ __launch_bounds__(256) void softmax_part(const float* __restrict__ sc,
                                                    float* __restrict__ pm, float* __restrict__ ps)
{
    const int col = blockIdx.x * 256 + threadIdx.x;
    const int seg = blockIdx.y, b = blockIdx.z;
    const float* p = sc + (long)b * SS * SS + (long)seg * 256 * SS + col;
    float m = -INFINITY, s = 0.f;
#pragma unroll 4
    for (int r = 0; r < 256; r++) {
        float v = p[(long)r * SS];
        float nm = fmaxf(m, v);
        s = s * __expf(m - nm) + __expf(v - nm);
        m = nm;
    }
    pm[((long)b * 8 + seg) * SS + col] = m;
    ps[((long)b * 8 + seg) * SS + col] = s;
}

__global__ __launch_bounds__(256) void softmax_comb(const float* __restrict__ pm,
                                                    const float* __restrict__ ps,
                                                    float* __restrict__ cm, float* __restrict__ ci)
{
    const int i = blockIdx.x * 256 + threadIdx.x;
    const int b = i >> 11, col = i & 2047;
    float M = -INFINITY;
#pragma unroll
    for (int s = 0; s < 8; s++) M = fmaxf(M, pm[((long)b * 8 + s) * SS + col]);
    float S = 0.f;
#pragma unroll
    for (int s = 0; s < 8; s++)
        S += ps[((long)b * 8 + s) * SS + col] * __expf(pm[((long)b * 8 + s) * SS + col] - M);
    cm[i] = M;
    ci[i] = 1.f / S;
}

__global__ __launch_bounds__(256) void softmax_norm(const float* __restrict__ sc,
                                                    const float* __restrict__ cm,
                                                    const float* __restrict__ ci,
                                                    __half* __restrict__ wh, __half* __restrict__ wl)
{
    const long e = ((long)blockIdx.x * 256 + threadIdx.x) * 4;
    const int b = (int)(e >> 22);
    const int col = (int)(e & 2047);
    float4 v = *reinterpret_cast<const float4*>(sc + e);
    float4 M = *reinterpret_cast<const float4*>(cm + (b << 11) + col);
    float4 I = *reinterpret_cast<const float4*>(ci + (b << 11) + col);
    float w0 = __expf(v.x - M.x) * I.x;
    float w1 = __expf(v.y - M.y) * I.y;
    float w2 = __expf(v.z - M.z) * I.z;
    float w3 = __expf(v.w - M.w) * I.w;
    wr_split(wh, wl, e, w0, w1);
    wr_split(wh, wl, e + 2, w2, w3);
}

// ---------------- launch ----------------
template <typename T>
static T* sym_addr(const void* sym) {
    void* p = nullptr;
    cudaGetSymbolAddress(&p, sym);
    return reinterpret_cast<T*>(p);
}

extern "C" void kernel_launch(void* const* d_in, const int* in_sizes, int n_in,
                              void* d_out, int out_size)
{
    const float* query = (const float*)d_in[0];
    const float* key   = (const float*)d_in[1];
    const float* value = (const float*)d_in[2];
    const float* Wq    = (const float*)d_in[3];
    const float* bq    = (const float*)d_in[4];
    const float* Wk    = (const float*)d_in[5];
    const float* bk    = (const float*)d_in[6];
    const float* Wv    = (const float*)d_in[7];
    const float* bv    = (const float*)d_in[8];
    const float* Wo    = (const float*)d_in[9];
    const float* bo    = (const float*)d_in[10];
    float* out = (float*)d_out;

    __half* Qh  = sym_addr<__half>(s_Qh);  __half* Ql  = sym_addr<__half>(s_Ql);
    __half* Kh  = sym_addr<__half>(s_Kh);  __half* Kl  = sym_addr<__half>(s_Kl);
    __half* Vh  = sym_addr<__half>(s_Vh);  __half* Vl  = sym_addr<__half>(s_Vl);
    __half* Wqh = sym_addr<__half>(s_Wqh); __half* Wql = sym_addr<__half>(s_Wql);
    __half* Wkh = sym_addr<__half>(s_Wkh); __half* Wkl = sym_addr<__half>(s_Wkl);
    __half* Wvh = sym_addr<__half>(s_Wvh); __half* Wvl = sym_addr<__half>(s_Wvl);
    __half* Woh = sym_addr<__half>(s_Woh); __half* Wol = sym_addr<__half>(s_Wol);
    __half* qh  = sym_addr<__half>(g_qh);  __half* ql  = sym_addr<__half>(g_ql);
    __half* kh  = sym_addr<__half>(g_kh);  __half* kl  = sym_addr<__half>(g_kl);
    __half* vh  = sym_addr<__half>(g_vh);  __half* vl  = sym_addr<__half>(g_vl);
    float*  sc  = sym_addr<float>(g_sc);
    __half* wh  = sym_addr<__half>(g_wh);  __half* wl  = sym_addr<__half>(g_wl);
    __half* ch  = sym_addr<__half>(g_ch);  __half* cl  = sym_addr<__half>(g_cl);
    float* pm = sym_addr<float>(g_pm);  float* ps = sym_addr<float>(g_ps);
    float* cm = sym_addr<float>(g_cm);  float* ci = sym_addr<float>(g_ci);

    cudaFuncSetAttribute(gemm_nt, cudaFuncAttributeMaxDynamicSharedMemorySize, NT_SMEM);
    cudaFuncSetAttribute(gemm_nn, cudaFuncAttributeMaxDynamicSharedMemorySize, NN_SMEM);

    // 0) split inputs + weights to hi/lo fp16
    const int nIn4 = MR * DD / 4;       // 2M float4
    const int nW4  = HH * DD / 4;       // 256K float4
    split_f32<<<nIn4 / 256, 256>>>((const float4*)query, (__half2*)Qh, (__half2*)Ql, nIn4);
    split_f32<<<nIn4 / 256, 256>>>((const float4*)key,   (__half2*)Kh, (__half2*)Kl, nIn4);
    split_f32<<<nIn4 / 256, 256>>>((const float4*)value, (__half2*)Vh, (__half2*)Vl, nIn4);
    split_f32<<<nW4 / 256, 256>>>((const float4*)Wq, (__half2*)Wqh, (__half2*)Wql, nW4);
    split_f32<<<nW4 / 256, 256>>>((const float4*)Wk, (__half2*)Wkh, (__half2*)Wkl, nW4);
    split_f32<<<nW4 / 256, 256>>>((const float4*)Wv, (__half2*)Wvh, (__half2*)Wvl, nW4);
    split_f32<<<nW4 / 256, 256>>>((const float4*)Wo, (__half2*)Woh, (__half2*)Wol, nW4);

    // 1) projections -> split fp16 outputs
    dim3 gp(HH / 128, MR / 128, 1);
    gemm_nt<<<gp, 256, NT_SMEM>>>(Qh, Ql, Wqh, Wql, bq, nullptr, qh, ql, MR, HH, DD, 0, 0, 0, 1.f);
    gemm_nt<<<gp, 256, NT_SMEM>>>(Kh, Kl, Wkh, Wkl, bk, nullptr, kh, kl, MR, HH, DD, 0, 0, 0, 1.f);
    gemm_nt<<<gp, 256, NT_SMEM>>>(Vh, Vl, Wvh, Wvl, bv, nullptr, vh, vl, MR, HH, DD, 0, 0, 0, 1.f);

    // 2) scores (fp32 out, scaled)
    dim3 gs(SS / 128, SS / 128, BB);
    gemm_nt<<<gs, 256, NT_SMEM>>>(qh, ql, kh, kl, nullptr, sc, nullptr, nullptr,
                                  SS, SS, HH, (long)SS * HH, (long)SS * HH, (long)SS * SS, SCALEF);

    // 3) softmax over query axis -> split fp16 weights
    softmax_part<<<dim3(SS / 256, 8, BB), 256>>>(sc, pm, ps);
    softmax_comb<<<dim3(BB * SS / 256), 256>>>(pm, ps, cm, ci);
    softmax_norm<<<dim3(BB * SS * SS / 4 / 256), 256>>>(sc, cm, ci, wh, wl);

    // 4) context NN: w[q,k] x v[k,h] -> ctx split
    dim3 gc(HH / 128, SS / 128, BB);
    gemm_nn<<<gc, 256, NN_SMEM>>>(wh, wl, vh, vl, ch, cl,
                                  SS, HH, SS, (long)SS * SS, (long)SS * HH, (long)SS * HH);

    // 5) output projection (fp32 out + bias)
    dim3 go(DD / 128, MR / 128, 1);
    gemm_nt<<<go, 256, NT_SMEM>>>(ch, cl, Woh, Wol, bo, out, nullptr, nullptr,
                                  MR, DD, HH, 0, 0, 0, 1.f);
}

// round 6
// speedup vs baseline: 1.2930x; 1.2930x over previous
#include <cuda_runtime.h>
#include <cuda_fp16.h>
#include <cstdint>
#include <math.h>

#define BB 4
#define SS 2048
#define DD 1024
#define HH 1024
#define SCALEF 0.125f

// ---------------- scratch (allocation-free rule) ----------------
__device__ float g_q[BB * SS * HH];
__device__ float g_k[BB * SS * HH];
__device__ float g_vT[BB * HH * SS];     // transposed V: [b][h][s]
__device__ float g_sc[BB * SS * SS];
__device__ float g_ctx[BB * SS * HH];
__device__ float g_pm[BB * 8 * SS];
__device__ float g_ps[BB * 8 * SS];
__device__ float g_colM[BB * SS];
__device__ float g_colI[BB * SS];

// ---------------- helpers ----------------
__device__ __forceinline__ uint32_t smem_u32(const void* p) {
    uint32_t a;
    asm("{ .reg .u64 t; cvta.to.shared.u64 t, %1; cvt.u32.u64 %0, t; }" : "=r"(a) : "l"(p));
    return a;
}

#define LDSM4(r, a) \
    asm volatile("ldmatrix.sync.aligned.m8n8.x4.shared.b16 {%0,%1,%2,%3}, [%4];" \
        : "=r"((r)[0]), "=r"((r)[1]), "=r"((r)[2]), "=r"((r)[3]) : "r"(a))

__device__ __forceinline__ void mma16816(float* c, const uint32_t* a, const uint32_t* b) {
    asm volatile("mma.sync.aligned.m16n8k16.row.col.f32.f16.f16.f32 "
        "{%0,%1,%2,%3}, {%4,%5,%6,%7}, {%8,%9}, {%0,%1,%2,%3};"
        : "+f"(c[0]), "+f"(c[1]), "+f"(c[2]), "+f"(c[3])
        : "r"(a[0]), "r"(a[1]), "r"(a[2]), "r"(a[3]), "r"(b[0]), "r"(b[1]));
}

// split fp32x4 into hi fp16x4 + lo fp16x4 (exact residual)
__device__ __forceinline__ void cvt_split(float4 v, uint32_t& h01, uint32_t& h23,
                                          uint32_t& l01, uint32_t& l23) {
    __half2 a = __floats2half2_rn(v.x, v.y);
    __half2 b = __floats2half2_rn(v.z, v.w);
    float r0 = v.x - __half2float(__low2half(a));
    float r1 = v.y - __half2float(__high2half(a));
    float r2 = v.z - __half2float(__low2half(b));
    float r3 = v.w - __half2float(__high2half(b));
    __half2 c = __floats2half2_rn(r0, r1);
    __half2 d = __floats2half2_rn(r2, r3);
    h01 = *reinterpret_cast<uint32_t*>(&a);
    h23 = *reinterpret_cast<uint32_t*>(&b);
    l01 = *reinterpret_cast<uint32_t*>(&c);
    l23 = *reinterpret_cast<uint32_t*>(&d);
}
__device__ __forceinline__ void cvt_hi(float4 v, uint32_t& h01, uint32_t& h23) {
    __half2 a = __floats2half2_rn(v.x, v.y);
    __half2 b = __floats2half2_rn(v.z, v.w);
    h01 = *reinterpret_cast<uint32_t*>(&a);
    h23 = *reinterpret_cast<uint32_t*>(&b);
}

// ---------------- HMMA split-fp16 NT GEMM ----------------
// C[m,n] = alpha * sum_k A[m,k] * B[n,k] (+ bias[n])
// tile 128x128, BK=32, 8 warps (2m x 4n), warp tile 64x32.
// smem rows padded to 40 halves (80B): gcd(5,8)=1 -> ldmatrix conflict-free.
// PASSES=3: hiA*hiB + hiA*loB + loA*hiB.  PASSES=2: hiA*hiB + hiA*loB (A-lo dropped).
#define LROW 80              // bytes per smem row
#define OFF_AL 10240
#define OFF_BH 20480
#define OFF_BL 30720
#define BUFSZ  40960
#define SMEM_SZ (2 * BUFSZ)

template <int PASSES, int TRANSV>
__global__ __launch_bounds__(256, 1) void gemm_hmma(
    const float* __restrict__ A, const float* __restrict__ B,
    const float* __restrict__ bias, float* __restrict__ C,
    int M, int N, int K, long sA, long sB, long sC, float alpha)
{
    extern __shared__ char smem[];
    const uint32_t sb = smem_u32(smem);
    const int tid  = threadIdx.x;
    const int lane = tid & 31;
    const int wid  = tid >> 5;
    const int wm   = wid & 1;       // 2 warps in m
    const int wn   = wid >> 1;      // 4 warps in n

    A += (long)blockIdx.z * sA;
    B += (long)blockIdx.z * sB;
    C += (long)blockIdx.z * sC;
    const int rowBase = blockIdx.y * 128;
    const int colBase = blockIdx.x * 128;

    const float* Ap = A + (long)rowBase * K;
    const float* Bp = B + (long)colBase * K;

    const int ldRow = tid >> 3;           // base row (stride 32 per i)
    const int ldC4  = (tid & 7) << 2;     // fp32 col within chunk

    float acc[4][4][4] = {};
    float4 pa[4], pb[4];

    const int nch = K >> 5;

    // prologue: load chunk 0, convert, store to buffer 0
#pragma unroll
    for (int i = 0; i < 4; i++) {
        pa[i] = *reinterpret_cast<const float4*>(Ap + (long)(ldRow + i * 32) * K + ldC4);
        pb[i] = *reinterpret_cast<const float4*>(Bp + (long)(ldRow + i * 32) * K + ldC4);
    }
#pragma unroll
    for (int i = 0; i < 4; i++) {
        uint32_t h01, h23, l01, l23;
        int off = (ldRow + i * 32) * LROW + ldC4 * 2;
        if (PASSES == 3) {
            cvt_split(pa[i], h01, h23, l01, l23);
            *reinterpret_cast<uint2*>(smem + off)          = make_uint2(h01, h23);
            *reinterpret_cast<uint2*>(smem + off + OFF_AL) = make_uint2(l01, l23);
        } else {
            cvt_hi(pa[i], h01, h23);
            *reinterpret_cast<uint2*>(smem + off)          = make_uint2(h01, h23);
        }
        cvt_split(pb[i], h01, h23, l01, l23);
        *reinterpret_cast<uint2*>(smem + off + OFF_BH) = make_uint2(h01, h23);
        *reinterpret_cast<uint2*>(smem + off + OFF_BL) = make_uint2(l01, l23);
    }
    __syncthreads();

    for (int c = 0; c < nch; c++) {
        // prefetch next chunk into registers
        if (c + 1 < nch) {
            const int k0 = (c + 1) << 5;
#pragma unroll
            for (int i = 0; i < 4; i++) {
                pa[i] = *reinterpret_cast<const float4*>(Ap + (long)(ldRow + i * 32) * K + k0 + ldC4);
                pb[i] = *reinterpret_cast<const float4*>(Bp + (long)(ldRow + i * 32) * K + k0 + ldC4);
            }
        }

        // compute from buffer c&1
        const uint32_t base = sb + (c & 1) * BUFSZ;
#pragma unroll
        for (int ks = 0; ks < 2; ks++) {
            uint32_t ah[4][4], al[4][4], bh[2][4], bl[2][4];
            const int kcA = ks * 16 + ((lane >> 4) << 3);
            const int mr  = wm * 64 + (lane & 15);
#pragma unroll
            for (int mt = 0; mt < 4; mt++) {
                uint32_t ad = base + (mr + mt * 16) * LROW + kcA * 2;
                LDSM4(ah[mt], ad);
                if (PASSES == 3) LDSM4(al[mt], ad + OFF_AL);
            }
            const int nr  = wn * 32 + (lane & 7) + ((lane >> 4) << 3);
            const int kcB = ks * 16 + (((lane >> 3) & 1) << 3);
#pragma unroll
            for (int np = 0; np < 2; np++) {
                uint32_t bd = base + OFF_BH + (nr + np * 16) * LROW + kcB * 2;
                LDSM4(bh[np], bd);
                LDSM4(bl[np], bd + (OFF_BL - OFF_BH));
            }
#pragma unroll
            for (int mt = 0; mt < 4; mt++)
#pragma unroll
                for (int nt = 0; nt < 4; nt++) {
                    const uint32_t* fh = &bh[nt >> 1][(nt & 1) * 2];
                    const uint32_t* fl = &bl[nt >> 1][(nt & 1) * 2];
                    mma16816(acc[mt][nt], ah[mt], fh);   // hiA * hiB
                    mma16816(acc[mt][nt], ah[mt], fl);   // hiA * loB
                    if (PASSES == 3) mma16816(acc[mt][nt], al[mt], fh);   // loA * hiB
                }
        }

        // stage next chunk into the other buffer
        if (c + 1 < nch) {
            char* dst = smem + ((c + 1) & 1) * BUFSZ;
#pragma unroll
            for (int i = 0; i < 4; i++) {
                uint32_t h01, h23, l01, l23;
                int off = (ldRow + i * 32) * LROW + ldC4 * 2;
                if (PASSES == 3) {
                    cvt_split(pa[i], h01, h23, l01, l23);
                    *reinterpret_cast<uint2*>(dst + off)          = make_uint2(h01, h23);
                    *reinterpret_cast<uint2*>(dst + off + OFF_AL) = make_uint2(l01, l23);
                } else {
                    cvt_hi(pa[i], h01, h23);
                    *reinterpret_cast<uint2*>(dst + off)          = make_uint2(h01, h23);
                }
                cvt_split(pb[i], h01, h23, l01, l23);
                *reinterpret_cast<uint2*>(dst + off + OFF_BH) = make_uint2(h01, h23);
                *reinterpret_cast<uint2*>(dst + off + OFF_BL) = make_uint2(l01, l23);
            }
            __syncthreads();
        }
    }

    // epilogue
#pragma unroll
    for (int mt = 0; mt < 4; mt++) {
        const int r0 = rowBase + wm * 64 + mt * 16 + (lane >> 2);
#pragma unroll
        for (int nt = 0; nt < 4; nt++) {
            const int c0 = colBase + wn * 32 + nt * 8 + (lane & 3) * 2;
            float v0 = acc[mt][nt][0] * alpha;
            float v1 = acc[mt][nt][1] * alpha;
            float v2 = acc[mt][nt][2] * alpha;
            float v3 = acc[mt][nt][3] * alpha;
            if (bias) {
                float b0 = __ldg(bias + c0), b1 = __ldg(bias + c0 + 1);
                v0 += b0; v1 += b1; v2 += b0; v3 += b1;
            }
            if (!TRANSV) {
                *reinterpret_cast<float2*>(C + (long)r0 * N + c0)       = make_float2(v0, v1);
                *reinterpret_cast<float2*>(C + (long)(r0 + 8) * N + c0) = make_float2(v2, v3);
            } else {
                // scatter into vT layout [b][h][s]; rows index b*2048+s, cols index h
                const int b0i = r0 >> 11, s0 = r0 & 2047;
                const int b1i = (r0 + 8) >> 11, s1 = (r0 + 8) & 2047;
                float* t0 = C + (long)b0i * (HH * (long)SS) + s0;
                float* t1 = C + (long)b1i * (HH * (long)SS) + s1;
                t0[(long)c0 * SS] = v0;       t0[(long)(c0 + 1) * SS] = v1;
                t1[(long)c0 * SS] = v2;       t1[(long)(c0 + 1) * SS] = v3;
            }
        }
    }
}

// ---------------- split softmax over QUERY axis ----------------
__global__ __launch_bounds__(256) void softmax_part(const float* __restrict__ sc,
                                                    float* __restrict__ pm, float* __restrict__ ps)
{
    const int col = blockIdx.x * 256 + threadIdx.x;
    const int seg = blockIdx.y, b = blockIdx.z;
    const float* p = sc + (long)b * SS * SS + (long)seg * 256 * SS + col;
    float m = -INFINITY, s = 0.f;
#pragma unroll 4
    for (int r = 0; r < 256; r++) {
        float v = p[(long)r * SS];
        float nm = fmaxf(m, v);
        s = s * __expf(m - nm) + __expf(v - nm);
        m = nm;
    }
    pm[((long)b * 8 + seg) * SS + col] = m;
    ps[((long)b * 8 + seg) * SS + col] = s;
}

__global__ __launch_bounds__(256) void softmax_comb(const float* __restrict__ pm,
                                                    const float* __restrict__ ps,
                                                    float* __restrict__ cm, float* __restrict__ ci)
{
    const int i = blockIdx.x * 256 + threadIdx.x;   // b*SS + col
    const int b = i >> 11, col = i & 2047;
    float M = -INFINITY;
#pragma unroll
    for (int s = 0; s < 8; s++) M = fmaxf(M, pm[((long)b * 8 + s) * SS + col]);
    float S = 0.f;
#pragma unroll
    for (int s = 0; s < 8; s++)
        S += ps[((long)b * 8 + s) * SS + col] * __expf(pm[((long)b * 8 + s) * SS + col] - M);
    cm[i] = M;
    ci[i] = 1.f / S;
}

__global__ __launch_bounds__(256) void softmax_norm(float* __restrict__ sc,
                                                    const float* __restrict__ cm,
                                                    const float* __restrict__ ci)
{
    const long e = ((long)blockIdx.x * 256 + threadIdx.x) * 4;
    const int b = (int)(e >> 22);
    const int col = (int)(e & 2047);
    float4 v = *reinterpret_cast<float4*>(sc + e);
    float4 M = *reinterpret_cast<const float4*>(cm + (b << 11) + col);
    float4 I = *reinterpret_cast<const float4*>(ci + (b << 11) + col);
    v.x = __expf(v.x - M.x) * I.x;
    v.y = __expf(v.y - M.y) * I.y;
    v.z = __expf(v.z - M.z) * I.z;
    v.w = __expf(v.w - M.w) * I.w;
    *reinterpret_cast<float4*>(sc + e) = v;
}

// ---------------- launch ----------------
static float* sym_addr(const void* sym) {
    void* p = nullptr;
    cudaGetSymbolAddress(&p, sym);
    return reinterpret_cast<float*>(p);
}

extern "C" void kernel_launch(void* const* d_in, const int* in_sizes, int n_in,
                              void* d_out, int out_size)
{
    const float* query = (const float*)d_in[0];
    const float* key   = (const float*)d_in[1];
    const float* value = (const float*)d_in[2];
    const float* Wq    = (const float*)d_in[3];
    const float* bq    = (const float*)d_in[4];
    const float* Wk    = (const float*)d_in[5];
    const float* bk    = (const float*)d_in[6];
    const float* Wv    = (const float*)d_in[7];
    const float* bv    = (const float*)d_in[8];
    const float* Wo    = (const float*)d_in[9];
    const float* bo    = (const float*)d_in[10];
    float* out = (float*)d_out;

    float* q   = sym_addr(g_q);
    float* k   = sym_addr(g_k);
    float* vT  = sym_addr(g_vT);
    float* sc  = sym_addr(g_sc);
    float* ctx = sym_addr(g_ctx);
    float* pm  = sym_addr(g_pm);
    float* ps  = sym_addr(g_ps);
    float* cm  = sym_addr(g_colM);
    float* ci  = sym_addr(g_colI);

    cudaFuncSetAttribute(gemm_hmma<3, 0>, cudaFuncAttributeMaxDynamicSharedMemorySize, SMEM_SZ);
    cudaFuncSetAttribute(gemm_hmma<2, 0>, cudaFuncAttributeMaxDynamicSharedMemorySize, SMEM_SZ);
    cudaFuncSetAttribute(gemm_hmma<2, 1>, cudaFuncAttributeMaxDynamicSharedMemorySize, SMEM_SZ);

    const int M = BB * SS;   // 8192

    // 1) Projections: [8192,1024] x [1024,1024]^T
    //    Q,K feed the softmax-critical scores path -> 3-pass; V tolerates 2-pass.
    dim3 gp(HH / 128, M / 128, 1);
    gemm_hmma<3, 0><<<gp, 256, SMEM_SZ>>>(query, Wq, bq, q,  M, HH, DD, 0, 0, 0, 1.f);
    gemm_hmma<3, 0><<<gp, 256, SMEM_SZ>>>(key,   Wk, bk, k,  M, HH, DD, 0, 0, 0, 1.f);
    gemm_hmma<2, 1><<<gp, 256, SMEM_SZ>>>(value, Wv, bv, vT, M, HH, DD, 0, 0, 0, 1.f);

    // 2) Scores per batch: [2048,1024] x [2048,1024]^T, *SCALE  (3-pass: accuracy-critical)
    dim3 gs(SS / 128, SS / 128, BB);
    gemm_hmma<3, 0><<<gs, 256, SMEM_SZ>>>(q, k, nullptr, sc, SS, SS, HH,
                                          (long)SS * HH, (long)SS * HH, (long)SS * SS, SCALEF);

    // 3) Softmax over the query axis
    softmax_part<<<dim3(SS / 256, 8, BB), 256>>>(sc, pm, ps);
    softmax_comb<<<dim3(BB * SS / 256), 256>>>(pm, ps, cm, ci);
    softmax_norm<<<dim3(BB * SS * SS / 4 / 256), 256>>>(sc, cm, ci);

    // 4) Context: [2048,2048] x vT[1024,2048]^T per batch -> [2048,1024]  (2-pass)
    dim3 gc(HH / 128, SS / 128, BB);
    gemm_hmma<2, 0><<<gc, 256, SMEM_SZ>>>(sc, vT, nullptr, ctx, SS, HH, SS,
                                          (long)SS * SS, (long)HH * SS, (long)SS * HH, 1.f);

    // 5) Output projection: [8192,1024] x [1024,1024]^T + bo  (2-pass)
    dim3 go(DD / 128, M / 128, 1);
    gemm_hmma<2, 0><<<go, 256, SMEM_SZ>>>(ctx, Wo, bo, out, M, DD, HH, 0, 0, 0, 1.f);
}